// round 4
// baseline (speedup 1.0000x reference)
#include <cuda_runtime.h>
#include <float.h>

#define ROW_LEN 4096
#define THREADS 256
#define V4 4                               // 256 * 4 * 4 = 4096 floats/row
#define NWARPS (THREADS / 32)              // 8
#define NUM_CTAS (148 * 5)                 // persistent grid, ~5 CTAs/SM

__global__ __launch_bounds__(THREADS)
void masked_softmax_persistent(const float* __restrict__ X,
                               const int* __restrict__ N,
                               float* __restrict__ out, int B) {
    const int tid = threadIdx.x;
    const int lane = tid & 31;
    const int wid = tid >> 5;

    __shared__ float red_m[NWARPS];
    __shared__ float red_s[NWARPS];
    __shared__ float sM, sS;

    int row = blockIdx.x;
    float4 v[V4];
    int n = 1;

    // ---- Prime the pipeline: load first row ----
    if (row < B) {
        const float4* xr = reinterpret_cast<const float4*>(X + (size_t)row * ROW_LEN);
#pragma unroll
        for (int i = 0; i < V4; i++) v[i] = __ldcs(&xr[tid + i * THREADS]);
        n = N[row];
    }

    for (; row < B; row += gridDim.x) {
        const int next = row + gridDim.x;

        // ---- Per-thread masked max ----
        float m_local = -FLT_MAX;
#pragma unroll
        for (int i = 0; i < V4; i++) {
            const int rem = n - (tid + i * THREADS) * 4;
            const float* f = reinterpret_cast<const float*>(&v[i]);
#pragma unroll
            for (int j = 0; j < 4; j++)
                if (j < rem) m_local = fmaxf(m_local, f[j]);
        }

        // ---- exp(x - m_local) in place + masked local sum ----
        float s = 0.0f;
#pragma unroll
        for (int i = 0; i < V4; i++) {
            const int rem = n - (tid + i * THREADS) * 4;
            float* f = reinterpret_cast<float*>(&v[i]);
#pragma unroll
            for (int j = 0; j < 4; j++) {
                const float ev = (j < rem) ? __expf(f[j] - m_local) : 0.0f;
                f[j] = ev;
                s += ev;
            }
        }

        // ---- Prefetch next row NOW: loads overlap reductions + stores ----
        float4 vn[V4];
        int n_next = 1;
        if (next < B) {
            const float4* xr = reinterpret_cast<const float4*>(X + (size_t)next * ROW_LEN);
#pragma unroll
            for (int i = 0; i < V4; i++) vn[i] = __ldcs(&xr[tid + i * THREADS]);
            n_next = N[next];
        }

        // ---- Single online (m,s) warp reduction ----
        float m = m_local;
#pragma unroll
        for (int o = 16; o > 0; o >>= 1) {
            const float mo = __shfl_xor_sync(0xFFFFFFFFu, m, o);
            const float so = __shfl_xor_sync(0xFFFFFFFFu, s, o);
            const float mn = fmaxf(m, mo);
            s = s * __expf(m - mn) + so * __expf(mo - mn);
            m = mn;
        }
        if (lane == 0) { red_m[wid] = m; red_s[wid] = s; }
        __syncthreads();

        // ---- Cross-warp merge in warp 0 ----
        if (wid == 0) {
            float m2 = (lane < NWARPS) ? red_m[lane] : -FLT_MAX;
            float s2 = (lane < NWARPS) ? red_s[lane] : 0.0f;
#pragma unroll
            for (int o = NWARPS / 2; o > 0; o >>= 1) {
                const float mo = __shfl_xor_sync(0xFFFFFFFFu, m2, o);
                const float so = __shfl_xor_sync(0xFFFFFFFFu, s2, o);
                const float mn = fmaxf(m2, mo);
                s2 = s2 * __expf(m2 - mn) + so * __expf(mo - mn);
                m2 = mn;
            }
            if (lane == 0) { sM = m2; sS = s2; }
        }
        __syncthreads();

        // ---- Rescale with thread-local max; store ----
        const float scale = __fdividef(__expf(m_local - sM), sS);

        float4* orow = reinterpret_cast<float4*>(out + (size_t)row * ROW_LEN);
#pragma unroll
        for (int i = 0; i < V4; i++) {
            const float* f = reinterpret_cast<const float*>(&v[i]);
            float4 o4;
            o4.x = f[0] * scale;
            o4.y = f[1] * scale;
            o4.z = f[2] * scale;
            o4.w = f[3] * scale;
            __stcs(&orow[tid + i * THREADS], o4);
        }

        // ---- Rotate pipeline (no barrier needed: sM/sS next write is
        //      ordered after everyone's next first __syncthreads) ----
#pragma unroll
        for (int i = 0; i < V4; i++) v[i] = vn[i];
        n = n_next;
    }
}

extern "C" void kernel_launch(void* const* d_in, const int* in_sizes, int n_in,
                              void* d_out, int out_size) {
    const float* X = (const float*)d_in[0];
    const int* N = (const int*)d_in[1];
    float* out = (float*)d_out;

    const int B = in_sizes[1];  // one int per row
    const int grid = (B < NUM_CTAS) ? B : NUM_CTAS;
    masked_softmax_persistent<<<grid, THREADS>>>(X, N, out, B);
}

// round 5
// speedup vs baseline: 1.2330x; 1.2330x over previous
#include <cuda_runtime.h>
#include <float.h>

#define ROW_LEN 4096
#define THREADS 256
#define V4 4                               // 256 * 4 * 4 = 4096 floats/row
#define NWARPS (THREADS / 32)              // 8

__global__ __launch_bounds__(THREADS, 8)
void masked_softmax_kernel(const float* __restrict__ X,
                           const int* __restrict__ N,
                           float* __restrict__ out) {
    const int row = blockIdx.x;
    const int tid = threadIdx.x;
    const int lane = tid & 31;
    const int wid = tid >> 5;

    const float4* __restrict__ xrow =
        reinterpret_cast<const float4*>(X + (size_t)row * ROW_LEN);
    float4* __restrict__ orow =
        reinterpret_cast<float4*>(out + (size_t)row * ROW_LEN);

    const int n = N[row];  // valid length in [1, ROW_LEN]

    __shared__ float red_m[NWARPS];
    __shared__ float red_s[NWARPS];
    __shared__ float sM, sS;

    // ---- Load entire row into registers (X read exactly once, streaming) ----
    float4 v[V4];
#pragma unroll
    for (int i = 0; i < V4; i++)
        v[i] = __ldcs(&xrow[tid + i * THREADS]);

    // ---- Per-thread masked max (no barriers) ----
    float m_local = -FLT_MAX;
#pragma unroll
    for (int i = 0; i < V4; i++) {
        const int rem = n - (tid + i * THREADS) * 4;
        const float* f = reinterpret_cast<const float*>(&v[i]);
#pragma unroll
        for (int j = 0; j < 4; j++)
            if (j < rem) m_local = fmaxf(m_local, f[j]);
    }

    // ---- exp(x - m_local) IN PLACE (kills the separate e[] array) ----
    float s = 0.0f;
#pragma unroll
    for (int i = 0; i < V4; i++) {
        const int rem = n - (tid + i * THREADS) * 4;
        float* f = reinterpret_cast<float*>(&v[i]);
#pragma unroll
        for (int j = 0; j < 4; j++) {
            const float ev = (j < rem) ? __expf(f[j] - m_local) : 0.0f;
            f[j] = ev;
            s += ev;
        }
    }

    // ---- Single online (m,s) warp reduction (m_local preserved) ----
    float m = m_local;
#pragma unroll
    for (int o = 16; o > 0; o >>= 1) {
        const float mo = __shfl_xor_sync(0xFFFFFFFFu, m, o);
        const float so = __shfl_xor_sync(0xFFFFFFFFu, s, o);
        const float mn = fmaxf(m, mo);
        s = s * __expf(m - mn) + so * __expf(mo - mn);
        m = mn;
    }
    if (lane == 0) { red_m[wid] = m; red_s[wid] = s; }
    __syncthreads();

    // ---- Cross-warp merge in warp 0 ----
    if (wid == 0) {
        float m2 = (lane < NWARPS) ? red_m[lane] : -FLT_MAX;
        float s2 = (lane < NWARPS) ? red_s[lane] : 0.0f;
#pragma unroll
        for (int o = NWARPS / 2; o > 0; o >>= 1) {
            const float mo = __shfl_xor_sync(0xFFFFFFFFu, m2, o);
            const float so = __shfl_xor_sync(0xFFFFFFFFu, s2, o);
            const float mn = fmaxf(m2, mo);
            s2 = s2 * __expf(m2 - mn) + so * __expf(mo - mn);
            m2 = mn;
        }
        if (lane == 0) { sM = m2; sS = s2; }
    }
    __syncthreads();

    // ---- Rescale with thread-local max; store ----
    const float scale = __fdividef(__expf(m_local - sM), sS);

#pragma unroll
    for (int i = 0; i < V4; i++) {
        const float* f = reinterpret_cast<const float*>(&v[i]);
        float4 o4;
        o4.x = f[0] * scale;
        o4.y = f[1] * scale;
        o4.z = f[2] * scale;
        o4.w = f[3] * scale;
        __stcs(&orow[tid + i * THREADS], o4);
    }
}

extern "C" void kernel_launch(void* const* d_in, const int* in_sizes, int n_in,
                              void* d_out, int out_size) {
    const float* X = (const float*)d_in[0];
    const int* N = (const int*)d_in[1];
    float* out = (float*)d_out;

    const int B = in_sizes[1];  // one int per row
    masked_softmax_kernel<<<B, THREADS>>>(X, N, out);
}

// round 6
// speedup vs baseline: 1.5304x; 1.2412x over previous
#include <cuda_runtime.h>
#include <float.h>

#define ROW_LEN 4096
#define THREADS 256
#define V4 4                               // 256 * 4 * 4 = 4096 floats/row
#define NWARPS (THREADS / 32)              // 8

__global__ __launch_bounds__(THREADS, 8)
void masked_softmax_kernel(const float* __restrict__ X,
                           const int* __restrict__ N,
                           float* __restrict__ out) {
    const int row = blockIdx.x;
    const int tid = threadIdx.x;
    const int lane = tid & 31;
    const int wid = tid >> 5;

    const float4* __restrict__ xrow =
        reinterpret_cast<const float4*>(X + (size_t)row * ROW_LEN);
    float4* __restrict__ orow =
        reinterpret_cast<float4*>(out + (size_t)row * ROW_LEN);

    const int n = N[row];  // valid length in [1, ROW_LEN]

    __shared__ float red_m[NWARPS];
    __shared__ float red_s[NWARPS];
    __shared__ float sM, sS;

    // ---- Load ONLY the valid prefix (predicated-off LDGs = no traffic) ----
    float4 v[V4];
#pragma unroll
    for (int i = 0; i < V4; i++) {
        const int base = (tid + i * THREADS) * 4;
        if (base < n) {
            v[i] = __ldcs(&xrow[tid + i * THREADS]);
        } else {
            v[i] = make_float4(0.0f, 0.0f, 0.0f, 0.0f);
        }
    }

    // ---- Per-thread masked max (skip invalid groups) ----
    float m_local = -FLT_MAX;
#pragma unroll
    for (int i = 0; i < V4; i++) {
        const int rem = n - (tid + i * THREADS) * 4;
        const float* f = reinterpret_cast<const float*>(&v[i]);
        if (rem > 0) {
#pragma unroll
            for (int j = 0; j < 4; j++)
                if (j < rem) m_local = fmaxf(m_local, f[j]);
        }
    }

    // ---- exp(x - m_local) in place + masked local sum (skip invalid groups) ----
    float s = 0.0f;
#pragma unroll
    for (int i = 0; i < V4; i++) {
        const int rem = n - (tid + i * THREADS) * 4;
        float* f = reinterpret_cast<float*>(&v[i]);
        if (rem > 0) {
#pragma unroll
            for (int j = 0; j < 4; j++) {
                const float ev = (j < rem) ? __expf(f[j] - m_local) : 0.0f;
                f[j] = ev;
                s += ev;
            }
        } else {
            f[0] = 0.0f; f[1] = 0.0f; f[2] = 0.0f; f[3] = 0.0f;
        }
    }

    // ---- Single online (m,s) warp reduction (m_local preserved) ----
    float m = m_local;
#pragma unroll
    for (int o = 16; o > 0; o >>= 1) {
        const float mo = __shfl_xor_sync(0xFFFFFFFFu, m, o);
        const float so = __shfl_xor_sync(0xFFFFFFFFu, s, o);
        const float mn = fmaxf(m, mo);
        s = s * __expf(m - mn) + so * __expf(mo - mn);
        m = mn;
    }
    if (lane == 0) { red_m[wid] = m; red_s[wid] = s; }
    __syncthreads();

    // ---- Cross-warp merge in warp 0 ----
    if (wid == 0) {
        float m2 = (lane < NWARPS) ? red_m[lane] : -FLT_MAX;
        float s2 = (lane < NWARPS) ? red_s[lane] : 0.0f;
#pragma unroll
        for (int o = NWARPS / 2; o > 0; o >>= 1) {
            const float mo = __shfl_xor_sync(0xFFFFFFFFu, m2, o);
            const float so = __shfl_xor_sync(0xFFFFFFFFu, s2, o);
            const float mn = fmaxf(m2, mo);
            s2 = s2 * __expf(m2 - mn) + so * __expf(mo - mn);
            m2 = mn;
        }
        if (lane == 0) { sM = m2; sS = s2; }
    }
    __syncthreads();

    // ---- Rescale with thread-local max; store (zeros beyond n) ----
    // Fully-masked threads: m_local = -FLT_MAX -> scale = 0 -> stores 0.
    const float scale = __fdividef(__expf(m_local - sM), sS);

#pragma unroll
    for (int i = 0; i < V4; i++) {
        const float* f = reinterpret_cast<const float*>(&v[i]);
        float4 o4;
        o4.x = f[0] * scale;
        o4.y = f[1] * scale;
        o4.z = f[2] * scale;
        o4.w = f[3] * scale;
        __stcs(&orow[tid + i * THREADS], o4);
    }
}

extern "C" void kernel_launch(void* const* d_in, const int* in_sizes, int n_in,
                              void* d_out, int out_size) {
    const float* X = (const float*)d_in[0];
    const int* N = (const int*)d_in[1];
    float* out = (float*)d_out;

    const int B = in_sizes[1];  // one int per row
    masked_softmax_kernel<<<B, THREADS>>>(X, N, out);
}